// round 9
// baseline (speedup 1.0000x reference)
#include <cuda_runtime.h>
#include <cstddef>
#include <cstdint>

// Problem constants
#define Bv 64
#define Nv 2048
#define Ev 16384
#define Fv 32
#define Hv 64
#define Kv 8
#define Cv 16
#define Gv 64
#define CKv 128          // C*K
#define NGv 131072       // N*G
#define CAPE 64          // max nodes per edge (mean 8)
#define CAPN 192         // max edges per node (mean 64); 192 = 6*32
#define CHUNK 6          // edges per cp.async chunk (2 slots x 6 x 4KB = 48KB)

typedef unsigned long long u64;

__device__ __forceinline__ u64 pack2(float lo, float hi) {
    u64 r; asm("mov.b64 %0,{%1,%2};" : "=l"(r) : "f"(lo), "f"(hi)); return r;
}
__device__ __forceinline__ void ffma2(u64& d, u64 a, u64 b) {
    asm("fma.rn.f32x2 %0,%1,%2,%0;" : "+l"(d) : "l"(a), "l"(b));
}
__device__ __forceinline__ void unpack2(float& lo, float& hi, u64 v) {
    asm("mov.b64 {%0,%1},%2;" : "=f"(lo), "=f"(hi) : "l"(v));
}
__device__ __forceinline__ float hsum2(u64 v) {
    float lo, hi; unpack2(lo, hi, v);
    return lo + hi;
}
__device__ __forceinline__ uint32_t s2u32(const void* p) {
    uint32_t a;
    asm("{ .reg .u64 t; cvta.to.shared.u64 t, %1; cvt.u32.u64 %0, t; }" : "=r"(a) : "l"(p));
    return a;
}
__device__ __forceinline__ void cp16(uint32_t dst, const float* src) {
    asm volatile("cp.async.cg.shared.global [%0], [%1], 16;" :: "r"(dst), "l"(src));
}
#define CP_COMMIT() asm volatile("cp.async.commit_group;")
#define CP_WAIT1()  asm volatile("cp.async.wait_group 1;")

// ---------------- scratch (device globals; no allocation) ----------------
__device__ float g_w[Ev * Kv];                 // per-edge kernel weights [E,K]
__device__ int   g_ecnt[Ev];
__device__ int   g_enodes[Ev * CAPE];          // rinc CSR: nodes per edge
__device__ int   g_ncnt[Nv];
__device__ int   g_nedges[Nv * CAPN];          // linc CSR: edges per node
__device__ float g_z[(size_t)Ev * Bv * Cv];    // z in (E,B,C) layout, 67MB

// ---------------- K0: edge MLP -> w[E,K] ----------------
__global__ void k0_edgew(const float* __restrict__ ef,
                         const float* __restrict__ w1, const float* __restrict__ b1,
                         const float* __restrict__ w2, const float* __restrict__ b2) {
    __shared__ float w1s[Hv * Fv];
    __shared__ float w2s[Kv * Hv];
    __shared__ float b1s[Hv];
    __shared__ float b2s[Kv];
    int t = threadIdx.x;
    for (int i = t; i < Hv * Fv; i += 128) w1s[i] = w1[i];
    for (int i = t; i < Kv * Hv; i += 128) w2s[i] = w2[i];
    if (t < Hv) b1s[t] = b1[t];
    if (t < Kv) b2s[t] = b2[t];
    __syncthreads();

    int e = blockIdx.x * 128 + t;
    float efr[Fv];
#pragma unroll
    for (int q = 0; q < Fv / 4; ++q)
        ((float4*)efr)[q] = ((const float4*)(ef + (size_t)e * Fv))[q];
    float wk[Kv];
#pragma unroll
    for (int k = 0; k < Kv; ++k) wk[k] = b2s[k];
    for (int j = 0; j < Hv; ++j) {
        float s = b1s[j];
#pragma unroll
        for (int f = 0; f < Fv; ++f) s += efr[f] * w1s[j * Fv + f];
        s = fmaxf(s, 0.0f);
#pragma unroll
        for (int k = 0; k < Kv; ++k) wk[k] += s * w2s[k * Hv + j];
    }
#pragma unroll
    for (int k = 0; k < Kv; ++k) g_w[e * Kv + k] = wk[k];
}

// ---------------- ordered sparse row scan (deterministic compaction) ---------
template <int COLS, int CAP, int UNROLL>
__device__ __forceinline__ void scan_row(const float* __restrict__ row,
                                         int* __restrict__ outp,
                                         int* __restrict__ cntp, int lane) {
    int cnt = 0;
    const float4* r4 = (const float4*)row;
    const unsigned lt = (1u << lane) - 1u;
    for (int g = 0; g < COLS / 128; g += UNROLL) {
        float4 v[UNROLL];
#pragma unroll
        for (int u = 0; u < UNROLL; ++u) v[u] = r4[(size_t)(g + u) * 32 + lane];
#pragma unroll
        for (int u = 0; u < UNROLL; ++u) {
            float a0 = v[u].x, a1 = v[u].y, a2 = v[u].z, a3 = v[u].w;
            unsigned m0 = __ballot_sync(0xffffffffu, a0 != 0.0f);
            unsigned m1 = __ballot_sync(0xffffffffu, a1 != 0.0f);
            unsigned m2 = __ballot_sync(0xffffffffu, a2 != 0.0f);
            unsigned m3 = __ballot_sync(0xffffffffu, a3 != 0.0f);
            int prefix = __popc(m0 & lt) + __popc(m1 & lt) + __popc(m2 & lt) + __popc(m3 & lt);
            int base = (g + u) * 128 + lane * 4;
            int own = 0;
            if (a0 != 0.0f) { int p = cnt + prefix + own; if (p < CAP) outp[p] = base + 0; own++; }
            if (a1 != 0.0f) { int p = cnt + prefix + own; if (p < CAP) outp[p] = base + 1; own++; }
            if (a2 != 0.0f) { int p = cnt + prefix + own; if (p < CAP) outp[p] = base + 2; own++; }
            if (a3 != 0.0f) { int p = cnt + prefix + own; if (p < CAP) outp[p] = base + 3; own++; }
            cnt += __popc(m0) + __popc(m1) + __popc(m2) + __popc(m3);
        }
    }
    if (lane == 0) *cntp = (cnt < CAP) ? cnt : CAP;
}

// K12: fused scans, linc rows FIRST (latency-bound, avoid tail)
__global__ void k12_scan(const float* __restrict__ rinc,
                         const float* __restrict__ linc) {
    int w = (blockIdx.x * blockDim.x + threadIdx.x) >> 5;
    int lane = threadIdx.x & 31;
    if (w < Nv) {
        scan_row<Ev, CAPN, 8>(linc + (size_t)w * Ev, g_nedges + (size_t)w * CAPN,
                              g_ncnt + w, lane);
    } else {
        int e = w - Nv;
        scan_row<Nv, CAPE, 4>(rinc + (size_t)e * Nv, g_enodes + (size_t)e * CAPE,
                              g_ecnt + e, lane);
    }
}

// ---------------- K3: warp-per-edge register gather (x stays in L2) -----------
__global__ void k3_gather(const float* __restrict__ x) {
    int e = (blockIdx.x * blockDim.x + threadIdx.x) >> 5;
    int lane = threadIdx.x & 31;

    int cnt = g_ecnt[e];
    const int* nl = g_enodes + (size_t)e * CAPE;
    int myn0 = (lane < cnt) ? nl[lane] : 0;
    int myn1 = (32 + lane < cnt) ? nl[32 + lane] : 0;

    const int boff = (lane >> 2) * (Nv * Cv / 4) + (lane & 3);

    float4 acc[8];
#pragma unroll
    for (int q = 0; q < 8; ++q) acc[q] = make_float4(0.f, 0.f, 0.f, 0.f);

    const float4* x4 = (const float4*)x;
    for (int i = 0; i < cnt; ++i) {
        int n = (i < 32) ? __shfl_sync(0xffffffffu, myn0, i)
                         : __shfl_sync(0xffffffffu, myn1, i - 32);
        const float4* xn = x4 + (size_t)n * (Cv / 4) + boff;
#pragma unroll
        for (int q = 0; q < 8; ++q) {
            float4 v = xn[(size_t)q * 8 * (Nv * Cv / 4)];
            acc[q].x += v.x; acc[q].y += v.y; acc[q].z += v.z; acc[q].w += v.w;
        }
    }

    float4* zw = (float4*)(g_z + (size_t)e * (Bv * Cv));
#pragma unroll
    for (int q = 0; q < 8; ++q) zw[q * 32 + lane] = acc[q];
}

// ---------------- K4 stage-2 inner loop (ODD = bq&1, compile-time) ----------
template <int ODD>
__device__ __forceinline__ void gemm_j(const u64* __restrict__ y_s,
                                       const float* __restrict__ gcw_s,
                                       int bq, int gq, u64 (&a2)[4][4]) {
    const u64* gc = (const u64*)gcw_s;
#pragma unroll 2
    for (int j2 = 0; j2 < 64; j2 += 2) {
        int p = (j2 ^ bq) & ~1;
        ulonglong2 yv[4], gv[4];
#pragma unroll
        for (int ib = 0; ib < 4; ++ib)
            yv[ib] = *(const ulonglong2*)(y_s + (bq * 4 + ib) * 64 + p);
#pragma unroll
        for (int ig = 0; ig < 4; ++ig)
            gv[ig] = *(const ulonglong2*)(gc + (gq * 4 + ig) * 64 + j2);
#pragma unroll
        for (int ib = 0; ib < 4; ++ib) {
            u64 yj = ODD ? yv[ib].y : yv[ib].x;
            ffma2(a2[ib][0], yj, gv[0].x); ffma2(a2[ib][1], yj, gv[1].x);
            ffma2(a2[ib][2], yj, gv[2].x); ffma2(a2[ib][3], yj, gv[3].x);
        }
#pragma unroll
        for (int ib = 0; ib < 4; ++ib) {
            u64 yj = ODD ? yv[ib].x : yv[ib].y;
            ffma2(a2[ib][0], yj, gv[0].y); ffma2(a2[ib][1], yj, gv[1].y);
            ffma2(a2[ib][2], yj, gv[2].y); ffma2(a2[ib][3], yj, gv[3].y);
        }
    }
}

// ---------------- K4: fused per-node y + GEMM + relu, cp.async z staging -----
// smem 65536 B overlay:
//   stage 1: zbuf [2 slots][CHUNK][1024 f] @0 (49152B) | wdup [CAPN][8] u64 @49152
//            ... wdup is 12288B -> ends 61440 | el_s @61440 (768B)
//   stage 2: gcw_s @0 (32KB) | y_s @32768 (32KB)
#define SMEM4 65536
#define WDUP_OFF 49152
#define EL_OFF   61440
__global__ void __launch_bounds__(256, 3) k4_main(const float* __restrict__ gcw,
                                                  const float* __restrict__ gcb,
                                                  float* __restrict__ out) {
    extern __shared__ char smem[];
    float* zbuf  = (float*)smem;
    u64*   wdup  = (u64*)(smem + WDUP_OFF);
    int*   el_s  = (int*)(smem + EL_OFF);
    float* gcw_s = (float*)smem;               // stage-2 overlay
    u64*   y_s   = (u64*)(smem + 32768);       // stage-2 overlay

    const uint32_t zbase = s2u32(smem);

    int n = blockIdx.x, t = threadIdx.x;
    int cnt = g_ncnt[n];
    int nch = (cnt + CHUNK - 1) / CHUNK;       // chunks of 6 edges

    // preamble: padded edge list + duplicated w pairs (pad -> edge 0, w = 0)
    if (t < CAPN) {
        int e = (t < cnt) ? g_nedges[(size_t)n * CAPN + t] : 0;
        el_s[t] = e;
        if (t < cnt) {
            float4 wa = *(const float4*)(g_w + (size_t)e * 8);
            float4 wb = *(const float4*)(g_w + (size_t)e * 8 + 4);
            wdup[t * 8 + 0] = pack2(wa.x, wa.x); wdup[t * 8 + 1] = pack2(wa.y, wa.y);
            wdup[t * 8 + 2] = pack2(wa.z, wa.z); wdup[t * 8 + 3] = pack2(wa.w, wa.w);
            wdup[t * 8 + 4] = pack2(wb.x, wb.x); wdup[t * 8 + 5] = pack2(wb.y, wb.y);
            wdup[t * 8 + 6] = pack2(wb.z, wb.z); wdup[t * 8 + 7] = pack2(wb.w, wb.w);
        } else {
#pragma unroll
            for (int k = 0; k < 8; ++k) wdup[t * 8 + k] = 0ull;
        }
    }
    __syncthreads();

    // issue one chunk of 6 edge tiles (4KB each) into slot c&1
    auto issue = [&](int c) {
        if (c < nch) {
            uint32_t dst = zbase + (uint32_t)(c & 1) * (CHUNK * 4096) + t * 16;
#pragma unroll
            for (int e = 0; e < CHUNK; ++e) {
                const float* src = g_z + (size_t)el_s[c * CHUNK + e] * (Bv * Cv) + t * 4;
                cp16(dst + e * 4096, src);
            }
        }
        CP_COMMIT();
    };

    // ---- stage 1: acc2[cp][k] += zpair(cp) * wdup(k); c-pair accumulation ----
    int b = t >> 2, cq = t & 3;
    const int zoff4 = b * 4 + cq;              // float4 index within a 4KB edge tile
    u64 acc2[2][8];
#pragma unroll
    for (int cp = 0; cp < 2; ++cp)
#pragma unroll
        for (int k = 0; k < 8; ++k) acc2[cp][k] = 0ull;

    issue(0); issue(1);
    for (int c = 0; c < nch; ++c) {
        CP_WAIT1();
        __syncthreads();
        const float4* zt = (const float4*)(zbuf + (c & 1) * (CHUNK * 1024));
        const ulonglong2* wd2 = (const ulonglong2*)(wdup + (size_t)c * CHUNK * 8);
#pragma unroll
        for (int e = 0; e < CHUNK; ++e) {
            float4 zv = zt[e * 256 + zoff4];
            u64 zp0 = pack2(zv.x, zv.y);       // natural register pairs
            u64 zp1 = pack2(zv.z, zv.w);
            ulonglong2 w01 = wd2[e * 4 + 0];
            ulonglong2 w23 = wd2[e * 4 + 1];
            ulonglong2 w45 = wd2[e * 4 + 2];
            ulonglong2 w67 = wd2[e * 4 + 3];
            ffma2(acc2[0][0], zp0, w01.x); ffma2(acc2[0][1], zp0, w01.y);
            ffma2(acc2[0][2], zp0, w23.x); ffma2(acc2[0][3], zp0, w23.y);
            ffma2(acc2[0][4], zp0, w45.x); ffma2(acc2[0][5], zp0, w45.y);
            ffma2(acc2[0][6], zp0, w67.x); ffma2(acc2[0][7], zp0, w67.y);
            ffma2(acc2[1][0], zp1, w01.x); ffma2(acc2[1][1], zp1, w01.y);
            ffma2(acc2[1][2], zp1, w23.x); ffma2(acc2[1][3], zp1, w23.y);
            ffma2(acc2[1][4], zp1, w45.x); ffma2(acc2[1][5], zp1, w45.y);
            ffma2(acc2[1][6], zp1, w67.x); ffma2(acc2[1][7], zp1, w67.y);
        }
        __syncthreads();                       // slot consumed by all before reuse
        issue(c + 2);
    }

    // repack c-pairs -> k-pairs (bit-exact; same as R7)
    float alo[2][8], ahi[2][8];
#pragma unroll
    for (int cp = 0; cp < 2; ++cp)
#pragma unroll
        for (int k = 0; k < 8; ++k) unpack2(alo[cp][k], ahi[cp][k], acc2[cp][k]);

    if (nch == 0) __syncthreads();             // keep barrier alignment for cnt==0
    // (when nch>0 the loop's trailing __syncthreads already separates stages)

    // ---- stage-2 overlay fill: y_s (swizzled) + gcw_s ----
    int bs = b >> 2;
#pragma unroll
    for (int ci = 0; ci < 4; ++ci) {
        int cp = ci >> 1, eo = ci & 1;
#pragma unroll
        for (int kq = 0; kq < 4; ++kq) {
            float v0 = eo ? ahi[cp][2 * kq]     : alo[cp][2 * kq];
            float v1 = eo ? ahi[cp][2 * kq + 1] : alo[cp][2 * kq + 1];
            int j = (cq * 4 + ci) * 4 + kq;
            y_s[b * 64 + (j ^ bs)] = pack2(v0, v1);
        }
    }
    for (int i = t; i < (Gv * CKv) / 4; i += 256)
        ((float4*)gcw_s)[i] = ((const float4*)gcw)[i];
    __syncthreads();

    // ---- stage 2: out[b][g] = relu(sum_ck y[b][ck]*gcw[g][ck] + gcb[g]) ----
    int bq = t & 15, gq = t >> 4;
    u64 a2[4][4];
#pragma unroll
    for (int ib = 0; ib < 4; ++ib)
#pragma unroll
        for (int ig = 0; ig < 4; ++ig) a2[ib][ig] = 0ull;

    if (bq & 1) gemm_j<1>(y_s, gcw_s, bq, gq, a2);
    else        gemm_j<0>(y_s, gcw_s, bq, gq, a2);

    float4 cb = *(const float4*)(gcb + gq * 4);
#pragma unroll
    for (int ib = 0; ib < 4; ++ib) {
        int bb = bq * 4 + ib;
        float4 o;
        o.x = fmaxf(hsum2(a2[ib][0]) + cb.x, 0.0f);
        o.y = fmaxf(hsum2(a2[ib][1]) + cb.y, 0.0f);
        o.z = fmaxf(hsum2(a2[ib][2]) + cb.z, 0.0f);
        o.w = fmaxf(hsum2(a2[ib][3]) + cb.w, 0.0f);
        *(float4*)(out + (size_t)bb * NGv + n * Gv + gq * 4) = o;
    }
}

// ---------------- launcher ----------------
extern "C" void kernel_launch(void* const* d_in, const int* in_sizes, int n_in,
                              void* d_out, int out_size) {
    const float* x    = (const float*)d_in[0];
    const float* linc = (const float*)d_in[1];
    const float* rinc = (const float*)d_in[2];
    const float* ef   = (const float*)d_in[3];
    const float* w1   = (const float*)d_in[4];
    const float* b1   = (const float*)d_in[5];
    const float* w2   = (const float*)d_in[6];
    const float* b2   = (const float*)d_in[7];
    const float* gcw  = (const float*)d_in[8];
    const float* gcb  = (const float*)d_in[9];
    float* out = (float*)d_out;

    (void)in_sizes; (void)n_in; (void)out_size;

    cudaFuncSetAttribute(k4_main, cudaFuncAttributeMaxDynamicSharedMemorySize, SMEM4);

    k0_edgew<<<Ev / 128, 128>>>(ef, w1, b1, w2, b2);
    k12_scan<<<(Ev + Nv) / 8, 256>>>(rinc, linc);   // linc rows first
    k3_gather<<<Ev / 8, 256>>>(x);                  // warp per edge
    k4_main<<<Nv, 256, SMEM4>>>(gcw, gcb, out);     // ncu launch idx 5
}